// round 10
// baseline (speedup 1.0000x reference)
#include <cuda_runtime.h>
#include <math.h>

// Indexed partials (no value atomics -> deterministic) + per-batch counters
__device__ double2 g_part[128 * 8];
__device__ int     g_cnt[128];       // zero-init; self-resetting each run

#define CPB 8                        // chunks per batch
#define CR  512                      // rows per chunk

// ---------------------------------------------------------------------------
// One 128-thread block per 512-row chunk (1024 blocks, single wave @7 CTA/SM).
// Octet mapping: lane covers eighth o8 of a row, 4 rows per warp-iteration.
// Chunk t -> own smem (+2 halo rows recomputed). Partial (s,ss) -> indexed
// global slot; 8th arriver per batch finalizes stats + head + output.
// ---------------------------------------------------------------------------
__global__ __launch_bounds__(128, 7)
void k_chunks(const float* __restrict__ x,
              const float* __restrict__ w1,
              const float* __restrict__ b1,
              const float* __restrict__ w2,
              const float* __restrict__ b2,
              const float* __restrict__ w3,
              const float* __restrict__ b3,
              float* __restrict__ out,
              int S, int dout)
{
    __shared__ float t_sh[CR + 8];         // chunk + 1 halo octet
    __shared__ double sh_s[4], sh_ss[4];
    __shared__ int sh_last;
    __shared__ alignas(16) float sh_stats[2];
    __shared__ alignas(16) float sh_o[64];

    const int bid = blockIdx.x;
    const int b   = bid >> 3;              // batch
    const int c   = bid & (CPB - 1);       // chunk within batch
    const int tid  = threadIdx.x;
    const int lane = tid & 31;
    const int o8   = lane & 7;             // eighth of a row
    const int sub  = lane >> 3;            // row within 4-row group
    const int wid  = tid >> 5;             // 4 warps

    const int row0 = c * CR;               // local row offset in batch
    const bool halo = (c < CPB - 1);
    const int ngroups = (halo ? CR + 8 : CR) >> 2;   // 130 : 128

    const float4* __restrict__ X = reinterpret_cast<const float4*>(x);
    const float4* __restrict__ W = reinterpret_cast<const float4*>(w1);

    // ---- Phase 1: stream this chunk (octet mapping, 4 LDG.128/lane) ----
    {
        float4 wa0[4], wa1[4];
        #pragma unroll
        for (int k = 0; k < 4; ++k) { wa0[k] = W[o8 + 8*k]; wa1[k] = W[32 + o8 + 8*k]; }
        const float bb0 = b1[0], bb1 = b1[1];
        const float c0 = w2[0], c1 = w2[1], cb = b2[0];

        for (int g = wid; g < ngroups; g += 4) {
            const int lrow = (g << 2) + sub;               // local row in chunk
            const size_t base = ((size_t)b * S + row0 + lrow) * 32 + o8;

            float4 v[4];
            #pragma unroll
            for (int k = 0; k < 4; ++k) v[k] = X[base + 8*k];

            float d0 = 0.f, d1 = 0.f;
            #pragma unroll
            for (int k = 0; k < 4; ++k) {
                d0 += v[k].x*wa0[k].x + v[k].y*wa0[k].y + v[k].z*wa0[k].z + v[k].w*wa0[k].w;
                d1 += v[k].x*wa1[k].x + v[k].y*wa1[k].y + v[k].z*wa1[k].z + v[k].w*wa1[k].w;
            }
            d0 += __shfl_xor_sync(0xffffffffu, d0, 1);
            d0 += __shfl_xor_sync(0xffffffffu, d0, 2);
            d0 += __shfl_xor_sync(0xffffffffu, d0, 4);
            d1 += __shfl_xor_sync(0xffffffffu, d1, 1);
            d1 += __shfl_xor_sync(0xffffffffu, d1, 2);
            d1 += __shfl_xor_sync(0xffffffffu, d1, 4);

            if (o8 == 0) {
                float h0 = fmaxf(d0 + bb0, 0.0f);
                float h1 = fmaxf(d1 + bb1, 0.0f);
                t_sh[lrow] = fmaf(c1, h1, fmaf(c0, h0, cb));
            }
        }
    }
    __syncthreads();

    // ---- Phase 2: partial stats for diffs i in [row0, row0+jmax) ----
    const int jmax = min(CR, (S - 2) - row0);   // 512, last chunk 510
    float fs = 0.f, fss = 0.f;
    for (int j = tid; j < jmax; j += 128) {
        float d = fabsf(t_sh[j + 2] - t_sh[j]);
        float l = logf(d + 1e-6f);
        fs += l;
        fss = fmaf(l, l, fss);
    }
    double s = (double)fs, ss = (double)fss;
    #pragma unroll
    for (int off = 16; off; off >>= 1) {
        s  += __shfl_xor_sync(0xffffffffu, s,  off);
        ss += __shfl_xor_sync(0xffffffffu, ss, off);
    }
    if (lane == 0) { sh_s[wid] = s; sh_ss[wid] = ss; }
    __syncthreads();
    if (tid == 0) {
        double ts  = sh_s[0] + sh_s[1] + sh_s[2] + sh_s[3];
        double tss = sh_ss[0] + sh_ss[1] + sh_ss[2] + sh_ss[3];
        g_part[bid] = make_double2(ts, tss);
    }

    // ---- publish; 8th arriver finalizes the batch ----
    __threadfence();
    __syncthreads();                    // g_part store issued before atomic
    if (tid == 0)
        sh_last = (atomicAdd(&g_cnt[b], 1) == CPB - 1) ? 1 : 0;
    __syncthreads();
    if (!sh_last) return;
    __threadfence();                    // acquire all 8 partials

    if (tid == 0) {
        double ts = 0.0, tss = 0.0;
        #pragma unroll
        for (int k = 0; k < CPB; ++k) {  // fixed order -> deterministic
            double2 p = g_part[b * CPB + k];
            ts += p.x; tss += p.y;
        }
        const double Nd = (double)(S - 2);
        double mean = ts / Nd;
        double var  = (tss - ts * ts / Nd) / (Nd - 1.0);
        if (var < 0.0) var = 0.0;
        sh_stats[0] = (float)mean;
        sh_stats[1] = (float)sqrt(var);
    }
    __syncthreads();

    if (tid < dout)
        sh_o[tid] = tanhf(sh_stats[0] * w3[2*tid] + sh_stats[1] * w3[2*tid + 1] + b3[tid]);
    __syncthreads();

    float4* __restrict__ ob = reinterpret_cast<float4*>(out + (size_t)b * dout * dout);
    const float4* __restrict__ so = reinterpret_cast<const float4*>(sh_o);
    const int total4 = (dout * dout) >> 2;   // 1024
    const int row4   = dout >> 2;            // 16
    for (int k = tid; k < total4; k += 128)
        ob[k] = so[k & (row4 - 1)];

    if (tid == 0) g_cnt[b] = 0;              // reset for next graph replay
}

extern "C" void kernel_launch(void* const* d_in, const int* in_sizes, int n_in,
                              void* d_out, int out_size)
{
    const float* x  = (const float*)d_in[0];
    const float* w1 = (const float*)d_in[1];
    const float* b1 = (const float*)d_in[2];
    const float* w2 = (const float*)d_in[3];
    const float* b2 = (const float*)d_in[4];
    const float* w3 = (const float*)d_in[5];
    const float* b3 = (const float*)d_in[6];
    float* out = (float*)d_out;

    const int DOUT = 64;
    const int B    = out_size / (DOUT * DOUT);   // 128
    const int rows = in_sizes[0] / 128;          // B * S
    const int S    = rows / B;                   // 4096

    k_chunks<<<B * CPB, 128>>>(x, w1, b1, w2, b2, w3, b3, out, S, DOUT);
}

// round 11
// speedup vs baseline: 1.0731x; 1.0731x over previous
#include <cuda_runtime.h>
#include <math.h>

// Indexed per-(batch,slot) partials + per-batch counters (zero-init, self-reset)
__device__ double2 g_part[128 * 4];
__device__ int     g_cnt[128];

#define NB 296            // blocks: 2 per SM, single wave

// Which block owns octet g (contiguous split of G octets over NB blocks)
__device__ __forceinline__ int block_of(int g, int base, int rem) {
    const int split = rem * (base + 1);
    return (g < split) ? g / (base + 1) : rem + (g - split) / base;
}

__global__ __launch_bounds__(256, 2)
void k_fused(const float* __restrict__ x,
             const float* __restrict__ w1,
             const float* __restrict__ b1,
             const float* __restrict__ w2,
             const float* __restrict__ b2,
             const float* __restrict__ w3,
             const float* __restrict__ b3,
             float* __restrict__ out,
             int S, int B, int dout)
{
    __shared__ float t_sh[224 * 8];            // up to 223 octets incl. halo
    __shared__ double sh_s[2][8], sh_ss[2][8];
    __shared__ int sh_fin[2];
    __shared__ alignas(16) float sh_stats[2];
    __shared__ alignas(16) float sh_o[64];

    const int G    = (B * S) >> 3;             // total octets (65536)
    const int base = G / NB, rem = G % NB;     // 221, 120
    const int i    = blockIdx.x;
    const int g0   = (i < rem) ? i * (base + 1)
                               : rem * (base + 1) + (i - rem) * base;
    const int g1   = g0 + base + (i < rem ? 1 : 0);
    const int opb  = S >> 3;                   // octets per batch (512)

    const int tid  = threadIdx.x;
    const int lane = tid & 31;
    const int wid  = tid >> 5;                 // 8 warps
    const int q    = lane & 3;                 // column slice within quad
    const int sub  = lane >> 2;                // row within octet

    const int gH    = (g1 % opb) ? 1 : 0;      // halo octet (same batch as tail)
    const int n_oct = g1 + gH - g0;

    const float4* __restrict__ X = reinterpret_cast<const float4*>(x);
    const float4* __restrict__ W = reinterpret_cast<const float4*>(w1);

    // ---- Phase 1: stream octets [g0, g0+n_oct) — proven quad-mapping loop ----
    {
        float4 wa0[8], wa1[8];
        #pragma unroll
        for (int k = 0; k < 8; ++k) { wa0[k] = W[q + 4*k]; wa1[k] = W[32 + q + 4*k]; }
        const float bb0 = b1[0], bb1 = b1[1];
        const float c0 = w2[0], c1 = w2[1], cb = b2[0];

        for (int lo = wid; lo < n_oct; lo += 8) {
            const int row = ((g0 + lo) << 3) + sub;
            const size_t bf4 = (size_t)row * 32 + q;

            float4 v[8];
            #pragma unroll
            for (int k = 0; k < 8; ++k) v[k] = X[bf4 + 4*k];

            float d0 = 0.f, d1 = 0.f;
            #pragma unroll
            for (int k = 0; k < 8; ++k) {
                d0 += v[k].x*wa0[k].x + v[k].y*wa0[k].y + v[k].z*wa0[k].z + v[k].w*wa0[k].w;
                d1 += v[k].x*wa1[k].x + v[k].y*wa1[k].y + v[k].z*wa1[k].z + v[k].w*wa1[k].w;
            }
            d0 += __shfl_xor_sync(0xffffffffu, d0, 1);
            d0 += __shfl_xor_sync(0xffffffffu, d0, 2);
            d1 += __shfl_xor_sync(0xffffffffu, d1, 1);
            d1 += __shfl_xor_sync(0xffffffffu, d1, 2);

            if (q == 0) {
                float h0 = fmaxf(d0 + bb0, 0.0f);
                float h1 = fmaxf(d1 + bb1, 0.0f);
                t_sh[(lo << 3) + sub] = fmaf(c1, h1, fmaf(c0, h0, cb));
            }
        }
    }
    __syncthreads();

    // ---- Phase 2: per-segment partial stats ----
    const int bA = g0 / opb;
    const int bB = (g1 - 1) / opb;
    const bool twoseg = (bB != bA);
    const int r0 = g0 << 3;

    int seg_lo[2], seg_hi[2];
    seg_lo[0] = r0;
    seg_hi[0] = min(twoseg ? (bA + 1) * S : (g1 << 3), (bA + 1) * S - 2);
    seg_lo[1] = (bA + 1) * S;
    seg_hi[1] = min(g1 << 3, (bB + 1) * S - 2);
    const int nsg = twoseg ? 2 : 1;

    #pragma unroll
    for (int s2 = 0; s2 < 2; ++s2) {
        float fs = 0.f, fss = 0.f;
        if (s2 < nsg) {
            for (int r = seg_lo[s2] + tid; r < seg_hi[s2]; r += 256) {
                float d = fabsf(t_sh[r + 2 - r0] - t_sh[r - r0]);
                float l = logf(d + 1e-6f);
                fs += l;
                fss = fmaf(l, l, fss);
            }
        }
        double s = (double)fs, ss = (double)fss;
        #pragma unroll
        for (int off = 16; off; off >>= 1) {
            s  += __shfl_xor_sync(0xffffffffu, s,  off);
            ss += __shfl_xor_sync(0xffffffffu, ss, off);
        }
        if (lane == 0) { sh_s[s2][wid] = s; sh_ss[s2][wid] = ss; }
    }
    __syncthreads();

    // ---- Publish: warp 0 reduces 8-warp partials, tid0 stores + atomics ----
    if (wid == 0) {
        double t0  = (lane < 8) ? sh_s[0][lane]  : 0.0;
        double t0s = (lane < 8) ? sh_ss[0][lane] : 0.0;
        double t1  = (lane < 8) ? sh_s[1][lane]  : 0.0;
        double t1s = (lane < 8) ? sh_ss[1][lane] : 0.0;
        #pragma unroll
        for (int off = 4; off; off >>= 1) {
            t0  += __shfl_xor_sync(0xffffffffu, t0,  off);
            t0s += __shfl_xor_sync(0xffffffffu, t0s, off);
            t1  += __shfl_xor_sync(0xffffffffu, t1,  off);
            t1s += __shfl_xor_sync(0xffffffffu, t1s, off);
        }
        if (lane == 0) {
            g_part[bA * 4 + (i - block_of(bA * opb, base, rem))] = make_double2(t0, t0s);
            if (twoseg)
                g_part[bB * 4 + 0] = make_double2(t1, t1s);   // we contain bB's first octet
            __threadfence();
            const int nA = block_of(bA * opb + opb - 1, base, rem)
                         - block_of(bA * opb, base, rem) + 1;
            sh_fin[0] = (atomicAdd(&g_cnt[bA], 1) == nA - 1) ? 1 : 0;
            if (twoseg) {
                const int nBseg = block_of(bB * opb + opb - 1, base, rem) - i + 1;
                sh_fin[1] = (atomicAdd(&g_cnt[bB], 1) == nBseg - 1) ? 1 : 0;
            } else sh_fin[1] = 0;
        }
    }
    __syncthreads();

    // ---- Epilogue for each batch this block finalized (0, 1, or 2) ----
    #pragma unroll
    for (int e = 0; e < 2; ++e) {
        if (!sh_fin[e]) continue;
        const int b = (e == 0) ? bA : bB;

        if (tid == 0) {
            __threadfence();                    // acquire other blocks' partials
            const int fb = block_of(b * opb, base, rem);
            const int nb = block_of(b * opb + opb - 1, base, rem) - fb + 1;
            double ts = 0.0, tss = 0.0;
            for (int k = 0; k < nb; ++k) {      // fixed order -> deterministic
                double2 p = g_part[b * 4 + k];
                ts += p.x; tss += p.y;
            }
            const double Nd = (double)(S - 2);
            double mean = ts / Nd;
            double var  = (tss - ts * ts / Nd) / (Nd - 1.0);
            if (var < 0.0) var = 0.0;
            sh_stats[0] = (float)mean;
            sh_stats[1] = (float)sqrt(var);
            g_cnt[b] = 0;                       // reset for next graph replay
        }
        __syncthreads();

        if (tid < dout)
            sh_o[tid] = tanhf(sh_stats[0] * w3[2*tid] + sh_stats[1] * w3[2*tid + 1] + b3[tid]);
        __syncthreads();

        float4* __restrict__ ob = reinterpret_cast<float4*>(out + (size_t)b * dout * dout);
        const float4* __restrict__ so = reinterpret_cast<const float4*>(sh_o);
        const int total4 = (dout * dout) >> 2;  // 1024
        const int row4   = dout >> 2;           // 16
        for (int k = tid; k < total4; k += 256)
            ob[k] = so[k & (row4 - 1)];
        __syncthreads();                        // protect sh_* before next e
    }
}

extern "C" void kernel_launch(void* const* d_in, const int* in_sizes, int n_in,
                              void* d_out, int out_size)
{
    const float* x  = (const float*)d_in[0];
    const float* w1 = (const float*)d_in[1];
    const float* b1 = (const float*)d_in[2];
    const float* w2 = (const float*)d_in[3];
    const float* b2 = (const float*)d_in[4];
    const float* w3 = (const float*)d_in[5];
    const float* b3 = (const float*)d_in[6];
    float* out = (float*)d_out;

    const int DOUT = 64;
    const int B    = out_size / (DOUT * DOUT);   // 128
    const int rows = in_sizes[0] / 128;          // B * S
    const int S    = rows / B;                   // 4096

    k_fused<<<NB, 256>>>(x, w1, b1, w2, b2, w3, b3, out, S, B, DOUT);
}